// round 2
// baseline (speedup 1.0000x reference)
#include <cuda_runtime.h>

#define Bz 512
#define Tz 256
#define Cz 384
#define Hz 64
#define BT (Bz*Tz)

typedef unsigned long long ull;

// Scratch for projected Q, K, V (allocation-free rule: __device__ globals)
__device__ float g_q[(size_t)BT * Hz];
__device__ float g_k[(size_t)BT * Hz];
__device__ float g_v[(size_t)BT * Hz];

__device__ __forceinline__ ull ffma2(ull a, ull b, ull c) {
    ull d;
    asm("fma.rn.f32x2 %0, %1, %2, %3;" : "=l"(d) : "l"(a), "l"(b), "l"(c));
    return d;
}
__device__ __forceinline__ ull pack2(float x, float y) {
    ull d;
    asm("mov.b64 %0, {%1, %2};" : "=l"(d) : "f"(x), "f"(y));
    return d;
}
__device__ __forceinline__ float2 unpack2(ull a) {
    float2 r;
    asm("mov.b64 {%0, %1}, %2;" : "=f"(r.x), "=f"(r.y) : "l"(a));
    return r;
}

// ---------------------------------------------------------------------------
// Kernel 1: fused QKV projection. [BT x 384] @ [384 x 192] + bias, fp32 f32x2.
// Block tile M=128, N=192 (q|k|v), Kc=8. 256 threads.
// Thread tile: 8 rows (ry + 16*i) x 12 cols (tx*12.. -> 6 f32x2 pairs).
// tx = tid>>4 => only 2 distinct tx per warp => B loads quasi-broadcast.
// ---------------------------------------------------------------------------
__global__ __launch_bounds__(256) void qkv_kernel(
    const float* __restrict__ x,
    const float* __restrict__ Wq, const float* __restrict__ bq,
    const float* __restrict__ Wk, const float* __restrict__ bk,
    const float* __restrict__ Wv, const float* __restrict__ bv)
{
    __shared__ __align__(16) float As[128][9];   // pad 9 -> conflict-free
    __shared__ __align__(16) float Bs[8][192];

    const int tid = threadIdx.x;
    const int m0  = blockIdx.x * 128;
    const int ry  = tid & 15;       // row group
    const int tx  = tid >> 4;       // col group (0..15)

    ull acc[8][6];
#pragma unroll
    for (int i = 0; i < 8; i++)
#pragma unroll
        for (int p = 0; p < 6; p++) acc[i][p] = 0ULL;

    for (int k0 = 0; k0 < Cz; k0 += 8) {
        // A tile: 128 rows x 8 cols; two threads per row, float4 each
        {
            int row = tid >> 1;
            int c4  = (tid & 1) * 4;
            float4 v = *(const float4*)(x + (size_t)(m0 + row) * Cz + k0 + c4);
            As[row][c4 + 0] = v.x; As[row][c4 + 1] = v.y;
            As[row][c4 + 2] = v.z; As[row][c4 + 3] = v.w;
        }
        // B tile: 8 rows x 192 cols = 768 float2, 3 per thread
#pragma unroll
        for (int it = 0; it < 3; it++) {
            int lin = it * 256 + tid;
            int kr  = lin / 96;
            int col = (lin % 96) * 2;
            int kg  = k0 + kr;
            float2 v;
            if (col < 64)        v = *(const float2*)(Wq + kg * 64 + col);
            else if (col < 128)  v = *(const float2*)(Wk + kg * 64 + (col - 64));
            else                 v = *(const float2*)(Wv + kg * 64 + (col - 128));
            Bs[kr][col]     = v.x;
            Bs[kr][col + 1] = v.y;
        }
        __syncthreads();

#pragma unroll
        for (int kk = 0; kk < 8; kk++) {
            ulonglong2 b01 = *(const ulonglong2*)&Bs[kk][tx * 12];
            ulonglong2 b23 = *(const ulonglong2*)&Bs[kk][tx * 12 + 4];
            ulonglong2 b45 = *(const ulonglong2*)&Bs[kk][tx * 12 + 8];
            ull bb0 = b01.x, bb1 = b01.y, bb2 = b23.x;
            ull bb3 = b23.y, bb4 = b45.x, bb5 = b45.y;
#pragma unroll
            for (int i = 0; i < 8; i++) {
                float a  = As[ry + 16 * i][kk];
                ull   a2 = pack2(a, a);
                acc[i][0] = ffma2(a2, bb0, acc[i][0]);
                acc[i][1] = ffma2(a2, bb1, acc[i][1]);
                acc[i][2] = ffma2(a2, bb2, acc[i][2]);
                acc[i][3] = ffma2(a2, bb3, acc[i][3]);
                acc[i][4] = ffma2(a2, bb4, acc[i][4]);
                acc[i][5] = ffma2(a2, bb5, acc[i][5]);
            }
        }
        __syncthreads();
    }

    // epilogue: add bias, scatter to g_q / g_k / g_v
#pragma unroll
    for (int i = 0; i < 8; i++) {
        const size_t row = (size_t)(m0 + ry + 16 * i);
#pragma unroll
        for (int p = 0; p < 6; p++) {
            float2 v = unpack2(acc[i][p]);
            int c = tx * 12 + 2 * p;   // even; never straddles the 64/128 splits
            float* dst; const float* bias; int cc;
            if (c < 64)       { dst = g_q; bias = bq; cc = c;       }
            else if (c < 128) { dst = g_k; bias = bk; cc = c - 64;  }
            else              { dst = g_v; bias = bv; cc = c - 128; }
            dst[row * Hz + cc]     = v.x + bias[cc];
            dst[row * Hz + cc + 1] = v.y + bias[cc + 1];
        }
    }
}

// ---------------------------------------------------------------------------
// Kernel 2: causal attention over one (batch, 64-query tile).
// grid (4, 512), 256 threads = 8 warps; warp w owns query rows w*8..w*8+7.
// Full K, V, S resident in dynamic smem (~211 KB -> 1 block/SM).
// ---------------------------------------------------------------------------
#define QS_STRIDE 68
#define KS_STRIDE 66
#define SMEM_FLOATS (64*QS_STRIDE + 256*KS_STRIDE + 256*64 + 64*256)
#define SMEM_BYTES  (SMEM_FLOATS * 4)

__global__ __launch_bounds__(256) void attn_kernel(float* __restrict__ out)
{
    extern __shared__ float sm[];
    float* Qs = sm;                         // [64][68]
    float* Ks = Qs + 64 * QS_STRIDE;        // [256][66]
    float* Vs = Ks + 256 * KS_STRIDE;       // [256][64]
    float* Ss = Vs + 256 * 64;              // [64][256]

    const int tid   = threadIdx.x;
    const int batch = blockIdx.y;
    const int q0    = blockIdx.x * 64;
    const int nkeys = q0 + 64;              // causal bound for this tile
    const float scale = 0.05103103630798287f;   // 384^-0.5 (C, per reference)

    const float* qg = g_q + ((size_t)batch * Tz + q0) * Hz;
    const float* kg = g_k + (size_t)batch * Tz * Hz;
    const float* vg = g_v + (size_t)batch * Tz * Hz;

    // load Q tile (64 x 64)
#pragma unroll
    for (int it = 0; it < 4; it++) {
        int f   = it * 256 + tid;
        int row = f >> 4;
        int c4  = (f & 15) * 4;
        float4 v = *(const float4*)(qg + row * 64 + c4);
        Qs[row * QS_STRIDE + c4 + 0] = v.x;
        Qs[row * QS_STRIDE + c4 + 1] = v.y;
        Qs[row * QS_STRIDE + c4 + 2] = v.z;
        Qs[row * QS_STRIDE + c4 + 3] = v.w;
    }
    // load K (stride 66) and V (stride 64)
    for (int f = tid; f < nkeys * 16; f += 256) {
        int row = f >> 4;
        int c4  = (f & 15) * 4;
        float4 kv = *(const float4*)(kg + row * 64 + c4);
        Ks[row * KS_STRIDE + c4 + 0] = kv.x;
        Ks[row * KS_STRIDE + c4 + 1] = kv.y;
        Ks[row * KS_STRIDE + c4 + 2] = kv.z;
        Ks[row * KS_STRIDE + c4 + 3] = kv.w;
        float4 vv = *(const float4*)(vg + row * 64 + c4);
        *(float4*)&Vs[row * 64 + c4] = vv;
    }
    __syncthreads();

    const int w    = tid >> 5;
    const int lane = tid & 31;
    const int rb   = w * 8;
    const int Lw     = q0 + rb + 8;          // exclusive key bound for this warp
    const int ntiles = (Lw + 31) >> 5;       // 32-key tiles to compute

    // ---- scores: warp tile 8 rows x 32 keys, packed over d ----
    for (int kt = 0; kt < ntiles; kt++) {
        const int key = kt * 32 + lane;
        const float* kp = &Ks[key * KS_STRIDE];
        ull acc[8];
#pragma unroll
        for (int r = 0; r < 8; r++) acc[r] = 0ULL;
#pragma unroll
        for (int d4 = 0; d4 < 64; d4 += 4) {
            ull k01 = *(const ull*)(kp + d4);
            ull k23 = *(const ull*)(kp + d4 + 2);
#pragma unroll
            for (int r = 0; r < 8; r++) {
                const float* qp = &Qs[(rb + r) * QS_STRIDE + d4];
                ull q01 = *(const ull*)(qp);
                ull q23 = *(const ull*)(qp + 2);
                acc[r] = ffma2(q01, k01, acc[r]);
                acc[r] = ffma2(q23, k23, acc[r]);
            }
        }
#pragma unroll
        for (int r = 0; r < 8; r++) {
            float2 h = unpack2(acc[r]);
            float s  = (h.x + h.y) * scale;
            int gq   = q0 + rb + r;
            Ss[(rb + r) * 256 + kt * 32 + lane] = (key <= gq) ? s : -1e30f;
        }
    }
    __syncwarp();

    // ---- softmax on this warp's 8 rows (lane owns its strided columns) ----
#pragma unroll
    for (int r = 0; r < 8; r++) {
        const int row = rb + r;
        float vals[8];
        float m = -1e30f;
        for (int j = 0; j < ntiles; j++) {
            vals[j] = Ss[row * 256 + j * 32 + lane];
            m = fmaxf(m, vals[j]);
        }
#pragma unroll
        for (int o = 16; o > 0; o >>= 1)
            m = fmaxf(m, __shfl_xor_sync(0xffffffffu, m, o));
        float sum = 0.f;
        for (int j = 0; j < ntiles; j++) {
            vals[j] = __expf(vals[j] - m);   // masked -1e30 -> 0
            sum += vals[j];
        }
#pragma unroll
        for (int o = 16; o > 0; o >>= 1)
            sum += __shfl_xor_sync(0xffffffffu, sum, o);
        float inv = 1.0f / sum;
        for (int j = 0; j < ntiles; j++)
            Ss[row * 256 + j * 32 + lane] = vals[j] * inv;
    }
    __syncwarp();

    // ---- PV: warp 8 rows x 64 dims; lane owns dims (lane, lane+32) ----
    float acc0[8], acc1[8];
#pragma unroll
    for (int r = 0; r < 8; r++) { acc0[r] = 0.f; acc1[r] = 0.f; }
    for (int j = 0; j < Lw; j += 4) {
        float v0[4], v1[4];
#pragma unroll
        for (int jj = 0; jj < 4; jj++) {
            v0[jj] = Vs[(j + jj) * 64 + lane];
            v1[jj] = Vs[(j + jj) * 64 + lane + 32];
        }
#pragma unroll
        for (int r = 0; r < 8; r++) {
            float4 wg = *(const float4*)&Ss[(rb + r) * 256 + j];
            acc0[r] += wg.x * v0[0] + wg.y * v0[1] + wg.z * v0[2] + wg.w * v0[3];
            acc1[r] += wg.x * v1[0] + wg.y * v1[1] + wg.z * v1[2] + wg.w * v1[3];
        }
    }

    // ---- write output [B, T, H] ----
    float* og = out + ((size_t)batch * Tz + q0 + rb) * Hz;
#pragma unroll
    for (int r = 0; r < 8; r++) {
        og[r * Hz + lane]      = acc0[r];
        og[r * Hz + lane + 32] = acc1[r];
    }
}

extern "C" void kernel_launch(void* const* d_in, const int* in_sizes, int n_in,
                              void* d_out, int out_size) {
    const float* x  = (const float*)d_in[0];
    const float* Wq = (const float*)d_in[1];
    const float* bq = (const float*)d_in[2];
    const float* Wk = (const float*)d_in[3];
    const float* bk = (const float*)d_in[4];
    const float* Wv = (const float*)d_in[5];
    const float* bv = (const float*)d_in[6];
    float* out = (float*)d_out;

    cudaFuncSetAttribute(attn_kernel,
                         cudaFuncAttributeMaxDynamicSharedMemorySize, SMEM_BYTES);

    qkv_kernel<<<BT / 128, 256>>>(x, Wq, bq, Wk, bk, Wv, bv);
    attn_kernel<<<dim3(Tz / 64, Bz), 256, SMEM_BYTES>>>(out);
}

// round 4
// speedup vs baseline: 1.7967x; 1.7967x over previous
#include <cuda_runtime.h>
#include <cuda_bf16.h>
#include <cstdint>

#define Bz 512
#define Tz 256
#define Cz 384
#define Hz 64
#define Nn 192
#define BT (Bz*Tz)

typedef unsigned long long ull;

// Scratch (allocation-free rule: __device__ globals)
__device__ float g_q[(size_t)BT * Hz];
__device__ float g_k[(size_t)BT * Hz];
__device__ float g_v[(size_t)BT * Hz];

// Pre-transposed weights Wt[n][k] = W[k][n], bf16 hi/lo split. [192][384].
__device__ __nv_bfloat16 g_wt_hi[Nn * Cz];
__device__ __nv_bfloat16 g_wt_lo[Nn * Cz];

__device__ __forceinline__ ull ffma2(ull a, ull b, ull c) {
    ull d;
    asm("fma.rn.f32x2 %0, %1, %2, %3;" : "=l"(d) : "l"(a), "l"(b), "l"(c));
    return d;
}
__device__ __forceinline__ float2 unpack2(ull a) {
    float2 r;
    asm("mov.b64 {%0, %1}, %2;" : "=f"(r.x), "=f"(r.y) : "l"(a));
    return r;
}
__device__ __forceinline__ uint32_t smem_u32(const void* p) {
    uint32_t a;
    asm("{ .reg .u64 t; cvta.to.shared.u64 t, %1; cvt.u32.u64 %0, t; }" : "=r"(a) : "l"(p));
    return a;
}
__device__ __forceinline__ void ldsm4(uint32_t* r, uint32_t addr) {
    asm volatile("ldmatrix.sync.aligned.m8n8.x4.shared.b16 {%0,%1,%2,%3}, [%4];"
                 : "=r"(r[0]), "=r"(r[1]), "=r"(r[2]), "=r"(r[3]) : "r"(addr));
}
__device__ __forceinline__ void mma16816(float* c, const uint32_t* a, const uint32_t* b) {
    asm volatile(
        "mma.sync.aligned.m16n8k16.row.col.f32.bf16.bf16.f32 "
        "{%0,%1,%2,%3}, {%4,%5,%6,%7}, {%8,%9}, {%0,%1,%2,%3};"
        : "+f"(c[0]), "+f"(c[1]), "+f"(c[2]), "+f"(c[3])
        : "r"(a[0]), "r"(a[1]), "r"(a[2]), "r"(a[3]), "r"(b[0]), "r"(b[1]));
}

// ---------------------------------------------------------------------------
// prep_w: W[k][n] fp32 -> Wt[n][k] bf16 hi/lo (row-major [192][384])
// ---------------------------------------------------------------------------
__global__ void prep_w(const float* __restrict__ Wq,
                       const float* __restrict__ Wk,
                       const float* __restrict__ Wv)
{
    int idx = blockIdx.x * blockDim.x + threadIdx.x;
    if (idx >= Cz * Nn) return;
    int k = idx / Nn, n = idx % Nn;
    float w;
    if (n < 64)       w = Wq[k * 64 + n];
    else if (n < 128) w = Wk[k * 64 + (n - 64)];
    else              w = Wv[k * 64 + (n - 128)];
    __nv_bfloat16 hi = __float2bfloat16(w);
    __nv_bfloat16 lo = __float2bfloat16(w - __bfloat162float(hi));
    g_wt_hi[n * Cz + k] = hi;
    g_wt_lo[n * Cz + k] = lo;
}

// ---------------------------------------------------------------------------
// qkv_tc: HMMA bf16-split GEMM. [BT x 384] @ [384 x 192] + bias.
// Block: 128 rows x 192 cols, 256 threads (8 warps, 4x2 warp grid).
// Warp tile 32x96 = 2 x 12 m16n8 fragments. 3 K-chunks of 128, 3 passes each.
// Smem rows padded to 136 bf16 (272B) -> conflict-free ldmatrix.
// ---------------------------------------------------------------------------
#define SA 136
#define AH_OFF 0
#define AL_OFF 34816
#define BH_OFF 69632
#define BL_OFF 121856
#define QKV_SMEM 174080

__global__ __launch_bounds__(256) void qkv_tc(
    const float* __restrict__ x,
    const float* __restrict__ bq, const float* __restrict__ bk,
    const float* __restrict__ bv)
{
    extern __shared__ char sm[];
    const uint32_t smb = smem_u32(sm);
    const int tid  = threadIdx.x;
    const int wid  = tid >> 5;
    const int lane = tid & 31;
    const int m0   = blockIdx.x * 128;
    const int wr   = wid & 3;     // 4 row groups of 32
    const int wc   = wid >> 2;    // 2 col groups of 96

    // ldmatrix per-lane source coordinates
    const int a_row = (lane & 7) + ((lane >> 3) & 1) * 8;
    const int a_k   = (lane >> 4) * 8;
    const int b_n   = (lane & 7) + (lane >> 4) * 8;
    const int b_k   = ((lane >> 3) & 1) * 8;

    float c[96];
#pragma unroll
    for (int i = 0; i < 96; i++) c[i] = 0.f;

    for (int chunk = 0; chunk < 3; chunk++) {
        // ---- A: load 128x128 fp32, split to bf16 hi/lo, store padded rows
#pragma unroll
        for (int it = 0; it < 8; it++) {
            int o   = it * 256 + tid;       // 2048 octets of 8 floats
            int row = o >> 4;
            int k8  = (o & 15) * 8;
            const float* src = x + (size_t)(m0 + row) * Cz + chunk * 128 + k8;
            float4 f0 = *(const float4*)src;
            float4 f1 = *(const float4*)(src + 4);
            float f[8] = {f0.x, f0.y, f0.z, f0.w, f1.x, f1.y, f1.z, f1.w};
            uint32_t h[4], l[4];
#pragma unroll
            for (int p = 0; p < 4; p++) {
                __nv_bfloat16 h0 = __float2bfloat16(f[2*p]);
                __nv_bfloat16 h1 = __float2bfloat16(f[2*p+1]);
                __nv_bfloat16 l0 = __float2bfloat16(f[2*p]   - __bfloat162float(h0));
                __nv_bfloat16 l1 = __float2bfloat16(f[2*p+1] - __bfloat162float(h1));
                __nv_bfloat162 hp = __halves2bfloat162(h0, h1);
                __nv_bfloat162 lp = __halves2bfloat162(l0, l1);
                h[p] = *(uint32_t*)&hp;
                l[p] = *(uint32_t*)&lp;
            }
            uint32_t off = (uint32_t)(row * SA + k8) * 2u;
            *(uint4*)(sm + AH_OFF + off) = make_uint4(h[0], h[1], h[2], h[3]);
            *(uint4*)(sm + AL_OFF + off) = make_uint4(l[0], l[1], l[2], l[3]);
        }
        // ---- B: copy pre-split Wt rows (192 x 128) into padded smem
#pragma unroll
        for (int it = 0; it < 12; it++) {
            int i  = it * 256 + tid;        // 3072 uint4 per array
            int n  = i >> 4;
            int j8 = (i & 15) * 8;
            size_t gsrc = (size_t)n * Cz + chunk * 128 + j8;
            uint32_t off = (uint32_t)(n * SA + j8) * 2u;
            *(uint4*)(sm + BH_OFF + off) = *(const uint4*)(g_wt_hi + gsrc);
            *(uint4*)(sm + BL_OFF + off) = *(const uint4*)(g_wt_lo + gsrc);
        }
        __syncthreads();

        // ---- compute: 3 passes (AhBh, AlBh, AhBl) x 8 k-steps of 16
        for (int pass = 0; pass < 3; pass++) {
            uint32_t abase = smb + ((pass == 1) ? AL_OFF : AH_OFF);
            uint32_t bbase = smb + ((pass == 2) ? BL_OFF : BH_OFF);
#pragma unroll
            for (int kk = 0; kk < 128; kk += 16) {
                uint32_t a0[4], a1[4];
                uint32_t addr0 = abase + (uint32_t)(((wr*32 + a_row) * SA) + kk + a_k) * 2u;
                ldsm4(a0, addr0);
                ldsm4(a1, addr0 + (uint32_t)(16 * SA) * 2u);
                uint32_t b[6][4];
#pragma unroll
                for (int jj = 0; jj < 6; jj++) {
                    uint32_t baddr = bbase +
                        (uint32_t)(((wc*96 + jj*16 + b_n) * SA) + kk + b_k) * 2u;
                    ldsm4(b[jj], baddr);
                }
#pragma unroll
                for (int j = 0; j < 12; j++) {
                    const uint32_t* bf = &b[j >> 1][(j & 1) * 2];
                    mma16816(c + (0*12 + j)*4, a0, bf);
                    mma16816(c + (1*12 + j)*4, a1, bf);
                }
            }
        }
        __syncthreads();
    }

    // ---- epilogue: bias + scatter to g_q / g_k / g_v
#pragma unroll
    for (int i = 0; i < 2; i++) {
        int row0 = m0 + wr*32 + i*16 + (lane >> 2);
#pragma unroll
        for (int j = 0; j < 12; j++) {
            int colg = wc*96 + j*8 + (lane & 3)*2;
            float* dst; const float* bias; int cc;
            if (colg < 64)       { dst = g_q; bias = bq; cc = colg;       }
            else if (colg < 128) { dst = g_k; bias = bk; cc = colg - 64;  }
            else                 { dst = g_v; bias = bv; cc = colg - 128; }
            float b0 = bias[cc], b1 = bias[cc + 1];
            const float* cp = c + (i*12 + j)*4;
            float2 v0 = make_float2(cp[0] + b0, cp[1] + b1);
            float2 v1 = make_float2(cp[2] + b0, cp[3] + b1);
            *(float2*)(dst + (size_t)row0 * Hz + cc)       = v0;
            *(float2*)(dst + (size_t)(row0 + 8) * Hz + cc) = v1;
        }
    }
}

// ---------------------------------------------------------------------------
// attn: causal attention, one block per (batch, 64-query tile). 512 threads =
// 16 warps; warp w owns 4 query rows. Full K,V,S in 211KB dynamic smem.
// ---------------------------------------------------------------------------
#define QS_STRIDE 68
#define KS_STRIDE 66
#define SMEM_FLOATS (64*QS_STRIDE + 256*KS_STRIDE + 256*64 + 64*256)
#define SMEM_BYTES  (SMEM_FLOATS * 4)

__global__ __launch_bounds__(512) void attn_kernel(float* __restrict__ out)
{
    extern __shared__ float smf[];
    float* Qs = smf;                        // [64][68]
    float* Ks = Qs + 64 * QS_STRIDE;        // [256][66]
    float* Vs = Ks + 256 * KS_STRIDE;       // [256][64]
    float* Ss = Vs + 256 * 64;              // [64][256]

    const int tid   = threadIdx.x;
    const int batch = blockIdx.y;
    const int q0    = blockIdx.x * 64;
    const int nkeys = q0 + 64;
    const float scale = 0.05103103630798287f;   // 384^-0.5 (C, per reference)

    const float* qg = g_q + ((size_t)batch * Tz + q0) * Hz;
    const float* kg = g_k + (size_t)batch * Tz * Hz;
    const float* vg = g_v + (size_t)batch * Tz * Hz;

#pragma unroll
    for (int it = 0; it < 2; it++) {
        int f   = it * 512 + tid;
        int row = f >> 4;
        int c4  = (f & 15) * 4;
        float4 v = *(const float4*)(qg + row * 64 + c4);
        Qs[row * QS_STRIDE + c4 + 0] = v.x;
        Qs[row * QS_STRIDE + c4 + 1] = v.y;
        Qs[row * QS_STRIDE + c4 + 2] = v.z;
        Qs[row * QS_STRIDE + c4 + 3] = v.w;
    }
    for (int f = tid; f < nkeys * 16; f += 512) {
        int row = f >> 4;
        int c4  = (f & 15) * 4;
        float4 kv = *(const float4*)(kg + row * 64 + c4);
        Ks[row * KS_STRIDE + c4 + 0] = kv.x;
        Ks[row * KS_STRIDE + c4 + 1] = kv.y;
        Ks[row * KS_STRIDE + c4 + 2] = kv.z;
        Ks[row * KS_STRIDE + c4 + 3] = kv.w;
        float4 vv = *(const float4*)(vg + row * 64 + c4);
        *(float4*)&Vs[row * 64 + c4] = vv;
    }
    __syncthreads();

    const int w    = tid >> 5;
    const int lane = tid & 31;
    const int rb   = w * 4;                  // 4 rows per warp
    const int Lw     = q0 + rb + 4;          // exclusive key bound
    const int ntiles = (Lw + 31) >> 5;

    // ---- scores ----
    for (int kt = 0; kt < ntiles; kt++) {
        const int key = kt * 32 + lane;
        const float* kp = &Ks[key * KS_STRIDE];
        ull acc[4];
#pragma unroll
        for (int r = 0; r < 4; r++) acc[r] = 0ULL;
#pragma unroll
        for (int d4 = 0; d4 < 64; d4 += 4) {
            ull k01 = *(const ull*)(kp + d4);
            ull k23 = *(const ull*)(kp + d4 + 2);
#pragma unroll
            for (int r = 0; r < 4; r++) {
                const float* qp = &Qs[(rb + r) * QS_STRIDE + d4];
                ull q01 = *(const ull*)(qp);
                ull q23 = *(const ull*)(qp + 2);
                acc[r] = ffma2(q01, k01, acc[r]);
                acc[r] = ffma2(q23, k23, acc[r]);
            }
        }
#pragma unroll
        for (int r = 0; r < 4; r++) {
            float2 h = unpack2(acc[r]);
            float s  = (h.x + h.y) * scale;
            int gq   = q0 + rb + r;
            Ss[(rb + r) * 256 + kt * 32 + lane] = (key <= gq) ? s : -1e30f;
        }
    }
    __syncwarp();

    // ---- softmax ----
#pragma unroll
    for (int r = 0; r < 4; r++) {
        const int row = rb + r;
        float vals[8];
        float m = -1e30f;
        for (int j = 0; j < ntiles; j++) {
            vals[j] = Ss[row * 256 + j * 32 + lane];
            m = fmaxf(m, vals[j]);
        }
#pragma unroll
        for (int o = 16; o > 0; o >>= 1)
            m = fmaxf(m, __shfl_xor_sync(0xffffffffu, m, o));
        float sum = 0.f;
        for (int j = 0; j < ntiles; j++) {
            vals[j] = __expf(vals[j] - m);
            sum += vals[j];
        }
#pragma unroll
        for (int o = 16; o > 0; o >>= 1)
            sum += __shfl_xor_sync(0xffffffffu, sum, o);
        float inv = 1.0f / sum;
        for (int j = 0; j < ntiles; j++)
            Ss[row * 256 + j * 32 + lane] = vals[j] * inv;
    }
    __syncwarp();

    // ---- PV ----
    float acc0[4], acc1[4];
#pragma unroll
    for (int r = 0; r < 4; r++) { acc0[r] = 0.f; acc1[r] = 0.f; }
    for (int j = 0; j < Lw; j += 4) {
        float v0[4], v1[4];
#pragma unroll
        for (int jj = 0; jj < 4; jj++) {
            v0[jj] = Vs[(j + jj) * 64 + lane];
            v1[jj] = Vs[(j + jj) * 64 + lane + 32];
        }
#pragma unroll
        for (int r = 0; r < 4; r++) {
            float4 wg = *(const float4*)&Ss[(rb + r) * 256 + j];
            acc0[r] += wg.x * v0[0] + wg.y * v0[1] + wg.z * v0[2] + wg.w * v0[3];
            acc1[r] += wg.x * v1[0] + wg.y * v1[1] + wg.z * v1[2] + wg.w * v1[3];
        }
    }

    float* og = out + ((size_t)batch * Tz + q0 + rb) * Hz;
#pragma unroll
    for (int r = 0; r < 4; r++) {
        og[r * Hz + lane]      = acc0[r];
        og[r * Hz + lane + 32] = acc1[r];
    }
}

extern "C" void kernel_launch(void* const* d_in, const int* in_sizes, int n_in,
                              void* d_out, int out_size) {
    const float* x  = (const float*)d_in[0];
    const float* Wq = (const float*)d_in[1];
    const float* bq = (const float*)d_in[2];
    const float* Wk = (const float*)d_in[3];
    const float* bk = (const float*)d_in[4];
    const float* Wv = (const float*)d_in[5];
    const float* bv = (const float*)d_in[6];
    float* out = (float*)d_out;

    cudaFuncSetAttribute(qkv_tc,
                         cudaFuncAttributeMaxDynamicSharedMemorySize, QKV_SMEM);
    cudaFuncSetAttribute(attn_kernel,
                         cudaFuncAttributeMaxDynamicSharedMemorySize, SMEM_BYTES);

    prep_w<<<(Cz * Nn + 255) / 256, 256>>>(Wq, Wk, Wv);
    qkv_tc<<<BT / 128, 256, QKV_SMEM>>>(x, bq, bk, bv);
    attn_kernel<<<dim3(Tz / 64, Bz), 512, SMEM_BYTES>>>(out);
}

// round 5
// speedup vs baseline: 5.4410x; 3.0283x over previous
#include <cuda_runtime.h>
#include <cuda_bf16.h>
#include <cuda_fp16.h>
#include <cstdint>

#define Bz 512
#define Tz 256
#define Cz 384
#define Hz 64
#define Nn 192
#define BT (Bz*Tz)

// Scratch (allocation-free rule: __device__ globals). fp16, q pre-scaled.
__device__ __half g_qh[(size_t)BT * Hz];
__device__ __half g_kh[(size_t)BT * Hz];
__device__ __half g_vh[(size_t)BT * Hz];

// Pre-transposed weights Wt[n][k] = W[k][n], bf16 hi/lo split. [192][384].
__device__ __nv_bfloat16 g_wt_hi[Nn * Cz];
__device__ __nv_bfloat16 g_wt_lo[Nn * Cz];

__device__ __forceinline__ uint32_t smem_u32(const void* p) {
    uint32_t a;
    asm("{ .reg .u64 t; cvta.to.shared.u64 t, %1; cvt.u32.u64 %0, t; }" : "=r"(a) : "l"(p));
    return a;
}
__device__ __forceinline__ void ldsm4(uint32_t* r, uint32_t addr) {
    asm volatile("ldmatrix.sync.aligned.m8n8.x4.shared.b16 {%0,%1,%2,%3}, [%4];"
                 : "=r"(r[0]), "=r"(r[1]), "=r"(r[2]), "=r"(r[3]) : "r"(addr));
}
__device__ __forceinline__ void mma_bf16(float* c, const uint32_t* a, const uint32_t* b) {
    asm volatile(
        "mma.sync.aligned.m16n8k16.row.col.f32.bf16.bf16.f32 "
        "{%0,%1,%2,%3}, {%4,%5,%6,%7}, {%8,%9}, {%0,%1,%2,%3};"
        : "+f"(c[0]), "+f"(c[1]), "+f"(c[2]), "+f"(c[3])
        : "r"(a[0]), "r"(a[1]), "r"(a[2]), "r"(a[3]), "r"(b[0]), "r"(b[1]));
}
__device__ __forceinline__ void mma_f16(float* c, const uint32_t* a, const uint32_t* b) {
    asm volatile(
        "mma.sync.aligned.m16n8k16.row.col.f32.f16.f16.f32 "
        "{%0,%1,%2,%3}, {%4,%5,%6,%7}, {%8,%9}, {%0,%1,%2,%3};"
        : "+f"(c[0]), "+f"(c[1]), "+f"(c[2]), "+f"(c[3])
        : "r"(a[0]), "r"(a[1]), "r"(a[2]), "r"(a[3]), "r"(b[0]), "r"(b[1]));
}
__device__ __forceinline__ uint32_t h2pack(float a, float b) {
    __half2 h = __floats2half2_rn(a, b);
    return *(uint32_t*)&h;
}

// ---------------------------------------------------------------------------
// prep_w: W[k][n] fp32 -> Wt[n][k] bf16 hi/lo (row-major [192][384])
// ---------------------------------------------------------------------------
__global__ void prep_w(const float* __restrict__ Wq,
                       const float* __restrict__ Wk,
                       const float* __restrict__ Wv)
{
    int idx = blockIdx.x * blockDim.x + threadIdx.x;
    if (idx >= Cz * Nn) return;
    int k = idx / Nn, n = idx % Nn;
    float w;
    if (n < 64)       w = Wq[k * 64 + n];
    else if (n < 128) w = Wk[k * 64 + (n - 64)];
    else              w = Wv[k * 64 + (n - 128)];
    __nv_bfloat16 hi = __float2bfloat16(w);
    __nv_bfloat16 lo = __float2bfloat16(w - __bfloat162float(hi));
    g_wt_hi[n * Cz + k] = hi;
    g_wt_lo[n * Cz + k] = lo;
}

// ---------------------------------------------------------------------------
// qkv_tc: HMMA bf16-split GEMM. [BT x 384] @ [384 x 192] + bias -> fp16.
// Block: 128 rows x 192 cols, 256 threads (8 warps, 4x2 warp grid).
// Warp tile 32x96 = 2 x 12 m16n8 fragments. 3 K-chunks of 128, 3 passes each.
// ---------------------------------------------------------------------------
#define SA 136
#define AH_OFF 0
#define AL_OFF 34816
#define BH_OFF 69632
#define BL_OFF 121856
#define QKV_SMEM 174080

__global__ __launch_bounds__(256) void qkv_tc(
    const float* __restrict__ x,
    const float* __restrict__ bq, const float* __restrict__ bk,
    const float* __restrict__ bv)
{
    extern __shared__ char sm[];
    const uint32_t smb = smem_u32(sm);
    const int tid  = threadIdx.x;
    const int wid  = tid >> 5;
    const int lane = tid & 31;
    const int m0   = blockIdx.x * 128;
    const int wr   = wid & 3;
    const int wc   = wid >> 2;

    const int a_row = (lane & 7) + ((lane >> 3) & 1) * 8;
    const int a_k   = (lane >> 4) * 8;
    const int b_n   = (lane & 7) + (lane >> 4) * 8;
    const int b_k   = ((lane >> 3) & 1) * 8;

    float c[96];
#pragma unroll
    for (int i = 0; i < 96; i++) c[i] = 0.f;

    for (int chunk = 0; chunk < 3; chunk++) {
        // ---- A: load 128x128 fp32, split to bf16 hi/lo
#pragma unroll
        for (int it = 0; it < 8; it++) {
            int o   = it * 256 + tid;
            int row = o >> 4;
            int k8  = (o & 15) * 8;
            const float* src = x + (size_t)(m0 + row) * Cz + chunk * 128 + k8;
            float4 f0 = *(const float4*)src;
            float4 f1 = *(const float4*)(src + 4);
            float f[8] = {f0.x, f0.y, f0.z, f0.w, f1.x, f1.y, f1.z, f1.w};
            uint32_t h[4], l[4];
#pragma unroll
            for (int p = 0; p < 4; p++) {
                __nv_bfloat16 h0 = __float2bfloat16(f[2*p]);
                __nv_bfloat16 h1 = __float2bfloat16(f[2*p+1]);
                __nv_bfloat16 l0 = __float2bfloat16(f[2*p]   - __bfloat162float(h0));
                __nv_bfloat16 l1 = __float2bfloat16(f[2*p+1] - __bfloat162float(h1));
                __nv_bfloat162 hp = __halves2bfloat162(h0, h1);
                __nv_bfloat162 lp = __halves2bfloat162(l0, l1);
                h[p] = *(uint32_t*)&hp;
                l[p] = *(uint32_t*)&lp;
            }
            uint32_t off = (uint32_t)(row * SA + k8) * 2u;
            *(uint4*)(sm + AH_OFF + off) = make_uint4(h[0], h[1], h[2], h[3]);
            *(uint4*)(sm + AL_OFF + off) = make_uint4(l[0], l[1], l[2], l[3]);
        }
        // ---- B: copy pre-split Wt rows (192 x 128)
#pragma unroll
        for (int it = 0; it < 12; it++) {
            int i  = it * 256 + tid;
            int n  = i >> 4;
            int j8 = (i & 15) * 8;
            size_t gsrc = (size_t)n * Cz + chunk * 128 + j8;
            uint32_t off = (uint32_t)(n * SA + j8) * 2u;
            *(uint4*)(sm + BH_OFF + off) = *(const uint4*)(g_wt_hi + gsrc);
            *(uint4*)(sm + BL_OFF + off) = *(const uint4*)(g_wt_lo + gsrc);
        }
        __syncthreads();

        for (int pass = 0; pass < 3; pass++) {
            uint32_t abase = smb + ((pass == 1) ? AL_OFF : AH_OFF);
            uint32_t bbase = smb + ((pass == 2) ? BL_OFF : BH_OFF);
#pragma unroll
            for (int kk = 0; kk < 128; kk += 16) {
                uint32_t a0[4], a1[4];
                uint32_t addr0 = abase + (uint32_t)(((wr*32 + a_row) * SA) + kk + a_k) * 2u;
                ldsm4(a0, addr0);
                ldsm4(a1, addr0 + (uint32_t)(16 * SA) * 2u);
                uint32_t b[6][4];
#pragma unroll
                for (int jj = 0; jj < 6; jj++) {
                    uint32_t baddr = bbase +
                        (uint32_t)(((wc*96 + jj*16 + b_n) * SA) + kk + b_k) * 2u;
                    ldsm4(b[jj], baddr);
                }
#pragma unroll
                for (int j = 0; j < 12; j++) {
                    const uint32_t* bf = &b[j >> 1][(j & 1) * 2];
                    mma_bf16(c + (0*12 + j)*4, a0, bf);
                    mma_bf16(c + (1*12 + j)*4, a1, bf);
                }
            }
        }
        __syncthreads();
    }

    // ---- epilogue: bias (+scale for q) -> fp16 scratch
    const float scale = 0.05103103630798287f;   // 384^-0.5 (C, per reference)
#pragma unroll
    for (int i = 0; i < 2; i++) {
        int row0 = m0 + wr*32 + i*16 + (lane >> 2);
#pragma unroll
        for (int j = 0; j < 12; j++) {
            int colg = wc*96 + j*8 + (lane & 3)*2;
            __half* dst; const float* bias; int cc; float sc;
            if (colg < 64)       { dst = g_qh; bias = bq; cc = colg;       sc = scale; }
            else if (colg < 128) { dst = g_kh; bias = bk; cc = colg - 64;  sc = 1.f;   }
            else                 { dst = g_vh; bias = bv; cc = colg - 128; sc = 1.f;   }
            float b0 = bias[cc], b1 = bias[cc + 1];
            const float* cp = c + (i*12 + j)*4;
            __half2 v0 = __floats2half2_rn((cp[0] + b0) * sc, (cp[1] + b1) * sc);
            __half2 v1 = __floats2half2_rn((cp[2] + b0) * sc, (cp[3] + b1) * sc);
            *(__half2*)(dst + (size_t)row0 * Hz + cc)       = v0;
            *(__half2*)(dst + (size_t)(row0 + 8) * Hz + cc) = v1;
        }
    }
}

// ---------------------------------------------------------------------------
// attn_hmma: flash-style causal attention on fp16 HMMA.
// Grid (2 q-blocks of 128, 512 batches), 256 threads = 8 warps.
// Warp w owns q-rows w*16..w*16+15 x all 64 keys of the current key block.
// Q frags in registers; K via non-trans ldmatrix; V stored transposed in smem;
// P stays in registers (C-frag -> fp16 A-frag). Online softmax.
// ---------------------------------------------------------------------------
#define ATT_SMEM ((128*72 + 64*72 + 64*72) * 2)

__global__ __launch_bounds__(256) void attn_hmma(float* __restrict__ out)
{
    extern __shared__ __half smh[];
    __half* Qs  = smh;                 // [128][72]
    __half* Ksm = smh + 128*72;        // [64 keys][72]
    __half* Vts = Ksm + 64*72;         // [64 dims][72] (transposed V)

    const int tid  = threadIdx.x;
    const int w    = tid >> 5;
    const int lane = tid & 31;
    const int batch = blockIdx.y;
    const int qb    = blockIdx.x;
    const int q0    = qb * 128;

    const __half* qg = g_qh + ((size_t)batch * Tz + q0) * Hz;
    const __half* kg = g_kh + (size_t)batch * Tz * Hz;
    const __half* vg = g_vh + (size_t)batch * Tz * Hz;

    // stage Q, then keep frags in registers
#pragma unroll
    for (int it = 0; it < 4; it++) {
        int i = it * 256 + tid;
        int row = i >> 3, c8 = (i & 7) * 8;
        *(uint4*)&Qs[row * 72 + c8] = *(const uint4*)(qg + row * Hz + c8);
    }
    __syncthreads();

    const int a_row = (lane & 7) + ((lane >> 3) & 1) * 8;
    const int a_k   = (lane >> 4) * 8;
    const int b_n   = (lane & 7) + (lane >> 4) * 8;
    const int b_k   = ((lane >> 3) & 1) * 8;

    uint32_t qf[4][4];
#pragma unroll
    for (int j = 0; j < 4; j++)
        ldsm4(qf[j], smem_u32(&Qs[(w*16 + a_row) * 72 + j*16 + a_k]));

    float o[8][4];
#pragma unroll
    for (int t = 0; t < 8; t++)
#pragma unroll
        for (int p = 0; p < 4; p++) o[t][p] = 0.f;
    float m0 = -1e30f, m1 = -1e30f, l0 = 0.f, l1 = 0.f;

    const int r     = lane >> 2;
    const int cpair = (lane & 3) * 2;
    const int rowg0 = q0 + w*16 + r;     // token index of C-frag row r
    const int kbmax = 2 * (qb + 1);

    for (int kb = 0; kb < kbmax; kb++) {
        __syncthreads();   // previous iteration's ldsm reads complete
        // K tile [64][64] -> smem
#pragma unroll
        for (int it = 0; it < 2; it++) {
            int i = it * 256 + tid;
            int key = i >> 3, c8 = (i & 7) * 8;
            *(uint4*)&Ksm[key * 72 + c8] =
                *(const uint4*)(kg + (size_t)(kb*64 + key) * Hz + c8);
        }
        // V tile, transposed store (2 keys x 8 dims per thread, half2 writes)
        {
            int k2 = (tid & 31) * 2;
            int c8 = (tid >> 5) * 8;
            uint4 va = *(const uint4*)(vg + (size_t)(kb*64 + k2)     * Hz + c8);
            uint4 vb = *(const uint4*)(vg + (size_t)(kb*64 + k2 + 1) * Hz + c8);
            const __half* ha = (const __half*)&va;
            const __half* hb = (const __half*)&vb;
#pragma unroll
            for (int d = 0; d < 8; d++)
                *(__half2*)&Vts[(c8 + d) * 72 + k2] = __halves2half2(ha[d], hb[d]);
        }
        __syncthreads();

        if (kb*64 > q0 + w*16 + 15) continue;   // fully masked for this warp

        // ---- S = Q K^T
        float s[8][4];
#pragma unroll
        for (int t = 0; t < 8; t++)
#pragma unroll
            for (int p = 0; p < 4; p++) s[t][p] = 0.f;
#pragma unroll
        for (int j = 0; j < 4; j++) {
            uint32_t bk4[4][4];
#pragma unroll
            for (int n = 0; n < 4; n++)
                ldsm4(bk4[n], smem_u32(&Ksm[(n*16 + b_n) * 72 + j*16 + b_k]));
#pragma unroll
            for (int t = 0; t < 8; t++)
                mma_f16(s[t], qf[j], &bk4[t >> 1][(t & 1) * 2]);
        }
        // ---- causal mask (only diagonal-crossing blocks)
        if (kb*64 + 63 > q0 + w*16) {
#pragma unroll
            for (int t = 0; t < 8; t++) {
                int col = kb*64 + t*8 + cpair;
                if (col     > rowg0)     s[t][0] = -1e30f;
                if (col + 1 > rowg0)     s[t][1] = -1e30f;
                if (col     > rowg0 + 8) s[t][2] = -1e30f;
                if (col + 1 > rowg0 + 8) s[t][3] = -1e30f;
            }
        }
        // ---- online softmax
        float a0 = -1e30f, a1 = -1e30f;
#pragma unroll
        for (int t = 0; t < 8; t++) {
            a0 = fmaxf(a0, fmaxf(s[t][0], s[t][1]));
            a1 = fmaxf(a1, fmaxf(s[t][2], s[t][3]));
        }
        a0 = fmaxf(a0, __shfl_xor_sync(0xffffffffu, a0, 1));
        a0 = fmaxf(a0, __shfl_xor_sync(0xffffffffu, a0, 2));
        a1 = fmaxf(a1, __shfl_xor_sync(0xffffffffu, a1, 1));
        a1 = fmaxf(a1, __shfl_xor_sync(0xffffffffu, a1, 2));
        float mn0 = fmaxf(m0, a0), mn1 = fmaxf(m1, a1);
        float al0 = __expf(m0 - mn0), al1 = __expf(m1 - mn1);
        m0 = mn0; m1 = mn1;
        float rs0 = 0.f, rs1 = 0.f;
#pragma unroll
        for (int t = 0; t < 8; t++) {
            s[t][0] = __expf(s[t][0] - m0);
            s[t][1] = __expf(s[t][1] - m0);
            s[t][2] = __expf(s[t][2] - m1);
            s[t][3] = __expf(s[t][3] - m1);
            rs0 += s[t][0] + s[t][1];
            rs1 += s[t][2] + s[t][3];
        }
        rs0 += __shfl_xor_sync(0xffffffffu, rs0, 1);
        rs0 += __shfl_xor_sync(0xffffffffu, rs0, 2);
        rs1 += __shfl_xor_sync(0xffffffffu, rs1, 1);
        rs1 += __shfl_xor_sync(0xffffffffu, rs1, 2);
        l0 = l0 * al0 + rs0;
        l1 = l1 * al1 + rs1;
#pragma unroll
        for (int t = 0; t < 8; t++) {
            o[t][0] *= al0; o[t][1] *= al0;
            o[t][2] *= al1; o[t][3] *= al1;
        }
        // ---- P C-frags -> fp16 A-frags
        uint32_t pf[4][4];
#pragma unroll
        for (int j = 0; j < 4; j++) {
            pf[j][0] = h2pack(s[2*j][0],   s[2*j][1]);
            pf[j][1] = h2pack(s[2*j][2],   s[2*j][3]);
            pf[j][2] = h2pack(s[2*j+1][0], s[2*j+1][1]);
            pf[j][3] = h2pack(s[2*j+1][2], s[2*j+1][3]);
        }
        // ---- O += P V
#pragma unroll
        for (int j = 0; j < 4; j++) {
            uint32_t bv[4][4];
#pragma unroll
            for (int dt = 0; dt < 4; dt++)
                ldsm4(bv[dt], smem_u32(&Vts[(dt*16 + b_n) * 72 + j*16 + b_k]));
#pragma unroll
            for (int t = 0; t < 8; t++)
                mma_f16(o[t], pf[j], &bv[t >> 1][(t & 1) * 2]);
        }
    }

    // ---- epilogue
    float inv0 = 1.f / l0, inv1 = 1.f / l1;
    float* og0 = out + ((size_t)batch * Tz + rowg0) * Hz;
    float* og1 = og0 + 8 * Hz;
#pragma unroll
    for (int t = 0; t < 8; t++) {
        *(float2*)(og0 + t*8 + cpair) = make_float2(o[t][0] * inv0, o[t][1] * inv0);
        *(float2*)(og1 + t*8 + cpair) = make_float2(o[t][2] * inv1, o[t][3] * inv1);
    }
}

extern "C" void kernel_launch(void* const* d_in, const int* in_sizes, int n_in,
                              void* d_out, int out_size) {
    const float* x  = (const float*)d_in[0];
    const float* Wq = (const float*)d_in[1];
    const float* bq = (const float*)d_in[2];
    const float* Wk = (const float*)d_in[3];
    const float* bk = (const float*)d_in[4];
    const float* Wv = (const float*)d_in[5];
    const float* bv = (const float*)d_in[6];
    float* out = (float*)d_out;

    cudaFuncSetAttribute(qkv_tc,
                         cudaFuncAttributeMaxDynamicSharedMemorySize, QKV_SMEM);
    cudaFuncSetAttribute(attn_hmma,
                         cudaFuncAttributeMaxDynamicSharedMemorySize, ATT_SMEM);

    prep_w<<<(Cz * Nn + 255) / 256, 256>>>(Wq, Wk, Wv);
    qkv_tc<<<BT / 128, 256, QKV_SMEM>>>(x, bq, bk, bv);
    attn_hmma<<<dim3(2, Bz), 256, ATT_SMEM>>>(out);
}

// round 6
// speedup vs baseline: 7.9116x; 1.4541x over previous
#include <cuda_runtime.h>
#include <cuda_bf16.h>
#include <cuda_fp16.h>
#include <cstdint>

#define Bz 512
#define Tz 256
#define Cz 384
#define Hz 64
#define Nn 192
#define BT (Bz*Tz)

// Scratch (allocation-free rule: __device__ globals). fp16, q pre-scaled.
__device__ __half g_qh[(size_t)BT * Hz];
__device__ __half g_kh[(size_t)BT * Hz];
__device__ __half g_vh[(size_t)BT * Hz];

// Pre-transposed weights Wt[n][k] = W[k][n], fp16. [192][384].
__device__ __half g_wt[Nn * Cz];

__device__ __forceinline__ uint32_t smem_u32(const void* p) {
    uint32_t a;
    asm("{ .reg .u64 t; cvta.to.shared.u64 t, %1; cvt.u32.u64 %0, t; }" : "=r"(a) : "l"(p));
    return a;
}
__device__ __forceinline__ void ldsm4(uint32_t* r, uint32_t addr) {
    asm volatile("ldmatrix.sync.aligned.m8n8.x4.shared.b16 {%0,%1,%2,%3}, [%4];"
                 : "=r"(r[0]), "=r"(r[1]), "=r"(r[2]), "=r"(r[3]) : "r"(addr));
}
__device__ __forceinline__ void mma_f16(float* c, const uint32_t* a, const uint32_t* b) {
    asm volatile(
        "mma.sync.aligned.m16n8k16.row.col.f32.f16.f16.f32 "
        "{%0,%1,%2,%3}, {%4,%5,%6,%7}, {%8,%9}, {%0,%1,%2,%3};"
        : "+f"(c[0]), "+f"(c[1]), "+f"(c[2]), "+f"(c[3])
        : "r"(a[0]), "r"(a[1]), "r"(a[2]), "r"(a[3]), "r"(b[0]), "r"(b[1]));
}
__device__ __forceinline__ uint32_t h2pack(float a, float b) {
    __half2 h = __floats2half2_rn(a, b);
    return *(uint32_t*)&h;
}
__device__ __forceinline__ void cp16(uint32_t smem_dst, const void* gsrc) {
    asm volatile("cp.async.cg.shared.global [%0], [%1], 16;"
                 :: "r"(smem_dst), "l"(gsrc) : "memory");
}

// ---------------------------------------------------------------------------
// prep_w: W[k][n] fp32 -> Wt[n][k] fp16 (row-major [192][384])
// ---------------------------------------------------------------------------
__global__ void prep_w(const float* __restrict__ Wq,
                       const float* __restrict__ Wk,
                       const float* __restrict__ Wv)
{
    int idx = blockIdx.x * blockDim.x + threadIdx.x;
    if (idx >= Cz * Nn) return;
    int k = idx / Nn, n = idx % Nn;
    float w;
    if (n < 64)       w = Wq[k * 64 + n];
    else if (n < 128) w = Wk[k * 64 + (n - 64)];
    else              w = Wv[k * 64 + (n - 128)];
    g_wt[n * Cz + k] = __float2half_rn(w);
}

// ---------------------------------------------------------------------------
// qkv_tc: single-pass fp16 HMMA GEMM. [BT x 384] @ [384 x 192] + bias -> fp16.
// Block: 128 rows x 192 cols, 256 threads (8 warps, 4x2 warp grid).
// Warp tile 32x96 = 2 x 12 m16n8 fragments.
// B (all 192x384 fp16, padded stride 392) resident in smem via cp.async.
// A chunked 3 x (128x128), fp32->fp16 converted in-kernel.
// ---------------------------------------------------------------------------
#define SA 136
#define SB 392
#define A_OFF 0
#define B_OFF 34816
#define QKV_SMEM (34816 + Nn*SB*2)   // 34816 + 150528 = 185344

__global__ __launch_bounds__(256) void qkv_tc(
    const float* __restrict__ x,
    const float* __restrict__ bq, const float* __restrict__ bk,
    const float* __restrict__ bv)
{
    extern __shared__ char sm[];
    const uint32_t smb = smem_u32(sm);
    const int tid  = threadIdx.x;
    const int wid  = tid >> 5;
    const int lane = tid & 31;
    const int m0   = blockIdx.x * 128;
    const int wr   = wid & 3;
    const int wc   = wid >> 2;

    const int a_row = (lane & 7) + ((lane >> 3) & 1) * 8;
    const int a_k   = (lane >> 4) * 8;
    const int b_n   = (lane & 7) + (lane >> 4) * 8;
    const int b_k   = ((lane >> 3) & 1) * 8;

    // ---- async-load ALL of B (192 x 384 fp16 -> padded stride 392)
#pragma unroll
    for (int it = 0; it < 36; it++) {
        int i = it * 256 + tid;          // 9216 16B-chunks
        int n = i / 48, c8 = (i % 48) * 8;
        cp16(smb + B_OFF + (uint32_t)(n * SB + c8) * 2u, g_wt + (size_t)n * Cz + c8);
    }
    asm volatile("cp.async.commit_group;" ::: "memory");

    float c[96];
#pragma unroll
    for (int i = 0; i < 96; i++) c[i] = 0.f;
    bool b_waited = false;

    for (int chunk = 0; chunk < 3; chunk++) {
        // ---- A: load 128x128 fp32, convert fp16, store padded rows
#pragma unroll
        for (int it = 0; it < 8; it++) {
            int o   = it * 256 + tid;
            int row = o >> 4;
            int k8  = (o & 15) * 8;
            const float* src = x + (size_t)(m0 + row) * Cz + chunk * 128 + k8;
            float4 f0 = *(const float4*)src;
            float4 f1 = *(const float4*)(src + 4);
            uint32_t h[4];
            h[0] = h2pack(f0.x, f0.y);
            h[1] = h2pack(f0.z, f0.w);
            h[2] = h2pack(f1.x, f1.y);
            h[3] = h2pack(f1.z, f1.w);
            *(uint4*)(sm + A_OFF + (uint32_t)(row * SA + k8) * 2u) =
                make_uint4(h[0], h[1], h[2], h[3]);
        }
        if (!b_waited) {
            asm volatile("cp.async.wait_group 0;" ::: "memory");
            b_waited = true;
        }
        __syncthreads();

        // ---- compute: 8 k-steps of 16 over this chunk
        uint32_t abase = smb + A_OFF;
        uint32_t bbase = smb + B_OFF;
#pragma unroll
        for (int kk = 0; kk < 128; kk += 16) {
            uint32_t a0[4], a1[4];
            uint32_t addr0 = abase + (uint32_t)(((wr*32 + a_row) * SA) + kk + a_k) * 2u;
            ldsm4(a0, addr0);
            ldsm4(a1, addr0 + (uint32_t)(16 * SA) * 2u);
            uint32_t b[6][4];
#pragma unroll
            for (int jj = 0; jj < 6; jj++) {
                uint32_t baddr = bbase +
                    (uint32_t)(((wc*96 + jj*16 + b_n) * SB) + chunk*128 + kk + b_k) * 2u;
                ldsm4(b[jj], baddr);
            }
#pragma unroll
            for (int j = 0; j < 12; j++) {
                const uint32_t* bf = &b[j >> 1][(j & 1) * 2];
                mma_f16(c + (0*12 + j)*4, a0, bf);
                mma_f16(c + (1*12 + j)*4, a1, bf);
            }
        }
        __syncthreads();
    }

    // ---- epilogue: bias (+scale for q) -> fp16 scratch
    const float scale = 0.05103103630798287f;   // 384^-0.5 (C, per reference)
#pragma unroll
    for (int i = 0; i < 2; i++) {
        int row0 = m0 + wr*32 + i*16 + (lane >> 2);
#pragma unroll
        for (int j = 0; j < 12; j++) {
            int colg = wc*96 + j*8 + (lane & 3)*2;
            __half* dst; const float* bias; int cc; float sc;
            if (colg < 64)       { dst = g_qh; bias = bq; cc = colg;       sc = scale; }
            else if (colg < 128) { dst = g_kh; bias = bk; cc = colg - 64;  sc = 1.f;   }
            else                 { dst = g_vh; bias = bv; cc = colg - 128; sc = 1.f;   }
            float b0 = bias[cc], b1 = bias[cc + 1];
            const float* cp = c + (i*12 + j)*4;
            __half2 v0 = __floats2half2_rn((cp[0] + b0) * sc, (cp[1] + b1) * sc);
            __half2 v1 = __floats2half2_rn((cp[2] + b0) * sc, (cp[3] + b1) * sc);
            *(__half2*)(dst + (size_t)row0 * Hz + cc)       = v0;
            *(__half2*)(dst + (size_t)(row0 + 8) * Hz + cc) = v1;
        }
    }
}

// ---------------------------------------------------------------------------
// attn_hmma: flash-style causal attention on fp16 HMMA.
// Grid (2 q-blocks of 128, 512 batches), 256 threads = 8 warps.
// ---------------------------------------------------------------------------
#define ATT_SMEM ((128*72 + 64*72 + 64*72) * 2)

__global__ __launch_bounds__(256) void attn_hmma(float* __restrict__ out)
{
    extern __shared__ __half smh[];
    __half* Qs  = smh;                 // [128][72]
    __half* Ksm = smh + 128*72;        // [64 keys][72]
    __half* Vts = Ksm + 64*72;         // [64 dims][72] (transposed V)

    const int tid  = threadIdx.x;
    const int w    = tid >> 5;
    const int lane = tid & 31;
    const int batch = blockIdx.y;
    const int qb    = blockIdx.x;
    const int q0    = qb * 128;

    const __half* qg = g_qh + ((size_t)batch * Tz + q0) * Hz;
    const __half* kg = g_kh + (size_t)batch * Tz * Hz;
    const __half* vg = g_vh + (size_t)batch * Tz * Hz;

#pragma unroll
    for (int it = 0; it < 4; it++) {
        int i = it * 256 + tid;
        int row = i >> 3, c8 = (i & 7) * 8;
        *(uint4*)&Qs[row * 72 + c8] = *(const uint4*)(qg + row * Hz + c8);
    }
    __syncthreads();

    const int a_row = (lane & 7) + ((lane >> 3) & 1) * 8;
    const int a_k   = (lane >> 4) * 8;
    const int b_n   = (lane & 7) + (lane >> 4) * 8;
    const int b_k   = ((lane >> 3) & 1) * 8;

    uint32_t qf[4][4];
#pragma unroll
    for (int j = 0; j < 4; j++)
        ldsm4(qf[j], smem_u32(&Qs[(w*16 + a_row) * 72 + j*16 + a_k]));

    float o[8][4];
#pragma unroll
    for (int t = 0; t < 8; t++)
#pragma unroll
        for (int p = 0; p < 4; p++) o[t][p] = 0.f;
    float m0 = -1e30f, m1 = -1e30f, l0 = 0.f, l1 = 0.f;

    const int r     = lane >> 2;
    const int cpair = (lane & 3) * 2;
    const int rowg0 = q0 + w*16 + r;
    const int kbmax = 2 * (qb + 1);

    for (int kb = 0; kb < kbmax; kb++) {
        __syncthreads();
#pragma unroll
        for (int it = 0; it < 2; it++) {
            int i = it * 256 + tid;
            int key = i >> 3, c8 = (i & 7) * 8;
            *(uint4*)&Ksm[key * 72 + c8] =
                *(const uint4*)(kg + (size_t)(kb*64 + key) * Hz + c8);
        }
        {
            int k2 = (tid & 31) * 2;
            int c8 = (tid >> 5) * 8;
            uint4 va = *(const uint4*)(vg + (size_t)(kb*64 + k2)     * Hz + c8);
            uint4 vb = *(const uint4*)(vg + (size_t)(kb*64 + k2 + 1) * Hz + c8);
            const __half* ha = (const __half*)&va;
            const __half* hb = (const __half*)&vb;
#pragma unroll
            for (int d = 0; d < 8; d++)
                *(__half2*)&Vts[(c8 + d) * 72 + k2] = __halves2half2(ha[d], hb[d]);
        }
        __syncthreads();

        if (kb*64 > q0 + w*16 + 15) continue;

        float s[8][4];
#pragma unroll
        for (int t = 0; t < 8; t++)
#pragma unroll
            for (int p = 0; p < 4; p++) s[t][p] = 0.f;
#pragma unroll
        for (int j = 0; j < 4; j++) {
            uint32_t bk4[4][4];
#pragma unroll
            for (int n = 0; n < 4; n++)
                ldsm4(bk4[n], smem_u32(&Ksm[(n*16 + b_n) * 72 + j*16 + b_k]));
#pragma unroll
            for (int t = 0; t < 8; t++)
                mma_f16(s[t], qf[j], &bk4[t >> 1][(t & 1) * 2]);
        }
        if (kb*64 + 63 > q0 + w*16) {
#pragma unroll
            for (int t = 0; t < 8; t++) {
                int col = kb*64 + t*8 + cpair;
                if (col     > rowg0)     s[t][0] = -1e30f;
                if (col + 1 > rowg0)     s[t][1] = -1e30f;
                if (col     > rowg0 + 8) s[t][2] = -1e30f;
                if (col + 1 > rowg0 + 8) s[t][3] = -1e30f;
            }
        }
        float a0 = -1e30f, a1 = -1e30f;
#pragma unroll
        for (int t = 0; t < 8; t++) {
            a0 = fmaxf(a0, fmaxf(s[t][0], s[t][1]));
            a1 = fmaxf(a1, fmaxf(s[t][2], s[t][3]));
        }
        a0 = fmaxf(a0, __shfl_xor_sync(0xffffffffu, a0, 1));
        a0 = fmaxf(a0, __shfl_xor_sync(0xffffffffu, a0, 2));
        a1 = fmaxf(a1, __shfl_xor_sync(0xffffffffu, a1, 1));
        a1 = fmaxf(a1, __shfl_xor_sync(0xffffffffu, a1, 2));
        float mn0 = fmaxf(m0, a0), mn1 = fmaxf(m1, a1);
        float al0 = __expf(m0 - mn0), al1 = __expf(m1 - mn1);
        m0 = mn0; m1 = mn1;
        float rs0 = 0.f, rs1 = 0.f;
#pragma unroll
        for (int t = 0; t < 8; t++) {
            s[t][0] = __expf(s[t][0] - m0);
            s[t][1] = __expf(s[t][1] - m0);
            s[t][2] = __expf(s[t][2] - m1);
            s[t][3] = __expf(s[t][3] - m1);
            rs0 += s[t][0] + s[t][1];
            rs1 += s[t][2] + s[t][3];
        }
        rs0 += __shfl_xor_sync(0xffffffffu, rs0, 1);
        rs0 += __shfl_xor_sync(0xffffffffu, rs0, 2);
        rs1 += __shfl_xor_sync(0xffffffffu, rs1, 1);
        rs1 += __shfl_xor_sync(0xffffffffu, rs1, 2);
        l0 = l0 * al0 + rs0;
        l1 = l1 * al1 + rs1;
#pragma unroll
        for (int t = 0; t < 8; t++) {
            o[t][0] *= al0; o[t][1] *= al0;
            o[t][2] *= al1; o[t][3] *= al1;
        }
        uint32_t pf[4][4];
#pragma unroll
        for (int j = 0; j < 4; j++) {
            pf[j][0] = h2pack(s[2*j][0],   s[2*j][1]);
            pf[j][1] = h2pack(s[2*j][2],   s[2*j][3]);
            pf[j][2] = h2pack(s[2*j+1][0], s[2*j+1][1]);
            pf[j][3] = h2pack(s[2*j+1][2], s[2*j+1][3]);
        }
#pragma unroll
        for (int j = 0; j < 4; j++) {
            uint32_t bv[4][4];
#pragma unroll
            for (int dt = 0; dt < 4; dt++)
                ldsm4(bv[dt], smem_u32(&Vts[(dt*16 + b_n) * 72 + j*16 + b_k]));
#pragma unroll
            for (int t = 0; t < 8; t++)
                mma_f16(o[t], pf[j], &bv[t >> 1][(t & 1) * 2]);
        }
    }

    float inv0 = 1.f / l0, inv1 = 1.f / l1;
    float* og0 = out + ((size_t)batch * Tz + rowg0) * Hz;
    float* og1 = og0 + 8 * Hz;
#pragma unroll
    for (int t = 0; t < 8; t++) {
        *(float2*)(og0 + t*8 + cpair) = make_float2(o[t][0] * inv0, o[t][1] * inv0);
        *(float2*)(og1 + t*8 + cpair) = make_float2(o[t][2] * inv1, o[t][3] * inv1);
    }
}

extern "C" void kernel_launch(void* const* d_in, const int* in_sizes, int n_in,
                              void* d_out, int out_size) {
    const float* x  = (const float*)d_in[0];
    const float* Wq = (const float*)d_in[1];
    const float* bq = (const float*)d_in[2];
    const float* Wk = (const float*)d_in[3];
    const float* bk = (const float*)d_in[4];
    const float* Wv = (const float*)d_in[5];
    const float* bv = (const float*)d_in[6];
    float* out = (float*)d_out;

    cudaFuncSetAttribute(qkv_tc,
                         cudaFuncAttributeMaxDynamicSharedMemorySize, QKV_SMEM);
    cudaFuncSetAttribute(attn_hmma,
                         cudaFuncAttributeMaxDynamicSharedMemorySize, ATT_SMEM);

    prep_w<<<(Cz * Nn + 255) / 256, 256>>>(Wq, Wk, Wv);
    qkv_tc<<<BT / 128, 256, QKV_SMEM>>>(x, bq, bk, bv);
    attn_hmma<<<dim3(2, Bz), 256, ATT_SMEM>>>(out);
}

// round 7
// speedup vs baseline: 9.5134x; 1.2025x over previous
#include <cuda_runtime.h>
#include <cuda_bf16.h>
#include <cuda_fp16.h>
#include <cstdint>

#define Bz 512
#define Tz 256
#define Cz 384
#define Hz 64
#define Nn 192
#define BT (Bz*Tz)

// Scratch (allocation-free rule: __device__ globals). fp16, q pre-scaled.
__device__ __half g_qh[(size_t)BT * Hz];
__device__ __half g_kh[(size_t)BT * Hz];
__device__ __half g_vh[(size_t)BT * Hz];

// Pre-transposed weights Wt[n][k] = W[k][n], fp16. [192][384].
__device__ __half g_wt[Nn * Cz];

__device__ __forceinline__ uint32_t smem_u32(const void* p) {
    uint32_t a;
    asm("{ .reg .u64 t; cvta.to.shared.u64 t, %1; cvt.u32.u64 %0, t; }" : "=r"(a) : "l"(p));
    return a;
}
__device__ __forceinline__ void ldsm4(uint32_t* r, uint32_t addr) {
    asm volatile("ldmatrix.sync.aligned.m8n8.x4.shared.b16 {%0,%1,%2,%3}, [%4];"
                 : "=r"(r[0]), "=r"(r[1]), "=r"(r[2]), "=r"(r[3]) : "r"(addr));
}
__device__ __forceinline__ void ldsm4t(uint32_t* r, uint32_t addr) {
    asm volatile("ldmatrix.sync.aligned.m8n8.x4.trans.shared.b16 {%0,%1,%2,%3}, [%4];"
                 : "=r"(r[0]), "=r"(r[1]), "=r"(r[2]), "=r"(r[3]) : "r"(addr));
}
__device__ __forceinline__ void mma_f16(float* c, const uint32_t* a, const uint32_t* b) {
    asm volatile(
        "mma.sync.aligned.m16n8k16.row.col.f32.f16.f16.f32 "
        "{%0,%1,%2,%3}, {%4,%5,%6,%7}, {%8,%9}, {%0,%1,%2,%3};"
        : "+f"(c[0]), "+f"(c[1]), "+f"(c[2]), "+f"(c[3])
        : "r"(a[0]), "r"(a[1]), "r"(a[2]), "r"(a[3]), "r"(b[0]), "r"(b[1]));
}
__device__ __forceinline__ uint32_t h2pack(float a, float b) {
    __half2 h = __floats2half2_rn(a, b);
    return *(uint32_t*)&h;
}
__device__ __forceinline__ void cp16(uint32_t smem_dst, const void* gsrc) {
    asm volatile("cp.async.cg.shared.global [%0], [%1], 16;"
                 :: "r"(smem_dst), "l"(gsrc) : "memory");
}

// ---------------------------------------------------------------------------
// prep_w: W[k][n] fp32 -> Wt[n][k] fp16 (row-major [192][384])
// ---------------------------------------------------------------------------
__global__ void prep_w(const float* __restrict__ Wq,
                       const float* __restrict__ Wk,
                       const float* __restrict__ Wv)
{
    int idx = blockIdx.x * blockDim.x + threadIdx.x;
    if (idx >= Cz * Nn) return;
    int k = idx / Nn, n = idx % Nn;
    float w;
    if (n < 64)       w = Wq[k * 64 + n];
    else if (n < 128) w = Wk[k * 64 + (n - 64)];
    else              w = Wv[k * 64 + (n - 128)];
    g_wt[n * Cz + k] = __float2half_rn(w);
}

// ---------------------------------------------------------------------------
// qkv_tc: single-pass fp16 HMMA GEMM, software-pipelined A double buffer.
// Block: 128 rows x 192 cols, 256 threads (8 warps, 4x2 warp grid).
// B (192x384 fp16, stride 392) resident via cp.async. A: 2 x 34KB buffers,
// next chunk's LDGs issued before / converted between compute halves.
// ---------------------------------------------------------------------------
#define SA 136
#define SB 392
#define ABUF 34816
#define B_OFF 69632
#define QKV_SMEM (B_OFF + Nn*SB*2)   // 220160

#define QKV_LDA(half, ch) { \
    _Pragma("unroll") \
    for (int it = 0; it < 4; it++) { \
        int o = ((half)*4 + it) * 256 + tid; \
        int row = o >> 4, k8 = (o & 15) * 8; \
        const float* src = x + (size_t)(m0 + row) * Cz + (ch) * 128 + k8; \
        pf[it*2]   = *(const uint4*)src; \
        pf[it*2+1] = *(const uint4*)(src + 4); \
    } }

#define QKV_STS(half, boff) { \
    _Pragma("unroll") \
    for (int it = 0; it < 4; it++) { \
        int o = ((half)*4 + it) * 256 + tid; \
        int row = o >> 4, k8 = (o & 15) * 8; \
        const float* fv = (const float*)&pf[it*2]; \
        *(uint4*)(sm + (boff) + (uint32_t)(row * SA + k8) * 2u) = \
            make_uint4(h2pack(fv[0], fv[1]), h2pack(fv[2], fv[3]), \
                       h2pack(fv[4], fv[5]), h2pack(fv[6], fv[7])); \
    } }

#define QKV_COMPUTE(ch, kk0) { \
    _Pragma("unroll") \
    for (int kk = (kk0); kk < (kk0) + 64; kk += 16) { \
        uint32_t a0[4], a1[4]; \
        uint32_t addr0 = abase + (uint32_t)(((wr*32 + a_row) * SA) + kk + a_k) * 2u; \
        ldsm4(a0, addr0); \
        ldsm4(a1, addr0 + (uint32_t)(16 * SA) * 2u); \
        uint32_t bfr[6][4]; \
        _Pragma("unroll") \
        for (int jj = 0; jj < 6; jj++) { \
            uint32_t baddr = smb + B_OFF + \
                (uint32_t)(((wc*96 + jj*16 + b_n) * SB) + (ch)*128 + kk + b_k) * 2u; \
            ldsm4(bfr[jj], baddr); \
        } \
        _Pragma("unroll") \
        for (int j = 0; j < 12; j++) { \
            const uint32_t* bf = &bfr[j >> 1][(j & 1) * 2]; \
            mma_f16(c + (0*12 + j)*4, a0, bf); \
            mma_f16(c + (1*12 + j)*4, a1, bf); \
        } \
    } }

__global__ __launch_bounds__(256) void qkv_tc(
    const float* __restrict__ x,
    const float* __restrict__ bq, const float* __restrict__ bk,
    const float* __restrict__ bv)
{
    extern __shared__ char sm[];
    const uint32_t smb = smem_u32(sm);
    const int tid  = threadIdx.x;
    const int wid  = tid >> 5;
    const int lane = tid & 31;
    const int m0   = blockIdx.x * 128;
    const int wr   = wid & 3;
    const int wc   = wid >> 2;

    const int a_row = (lane & 7) + ((lane >> 3) & 1) * 8;
    const int a_k   = (lane >> 4) * 8;
    const int b_n   = (lane & 7) + (lane >> 4) * 8;
    const int b_k   = ((lane >> 3) & 1) * 8;

    // ---- async-load ALL of B (192 x 384 fp16 -> padded stride 392)
#pragma unroll
    for (int it = 0; it < 36; it++) {
        int i = it * 256 + tid;
        int n = i / 48, c8 = (i % 48) * 8;
        cp16(smb + B_OFF + (uint32_t)(n * SB + c8) * 2u, g_wt + (size_t)n * Cz + c8);
    }
    asm volatile("cp.async.commit_group;" ::: "memory");

    float c[96];
#pragma unroll
    for (int i = 0; i < 96; i++) c[i] = 0.f;

    // ---- A chunk 0 -> buf0 (overlapped with B cp.async)
    {
        uint4 pf[8];
        QKV_LDA(0, 0); QKV_STS(0, 0);
        QKV_LDA(1, 0); QKV_STS(1, 0);
    }
    asm volatile("cp.async.wait_group 0;" ::: "memory");
    __syncthreads();

    for (int chunk = 0; chunk < 3; chunk++) {
        const uint32_t abase  = smb + (uint32_t)((chunk & 1) * ABUF);
        const uint32_t nb_off = (uint32_t)(((chunk + 1) & 1) * ABUF);
        uint4 pf[8];
        if (chunk < 2) QKV_LDA(0, chunk + 1);
        QKV_COMPUTE(chunk, 0)
        if (chunk < 2) { QKV_STS(0, nb_off); QKV_LDA(1, chunk + 1); }
        QKV_COMPUTE(chunk, 64)
        if (chunk < 2) QKV_STS(1, nb_off);
        __syncthreads();
    }

    // ---- epilogue: bias (+scale for q) -> fp16 scratch
    const float scale = 0.05103103630798287f;   // 384^-0.5 (C, per reference)
#pragma unroll
    for (int i = 0; i < 2; i++) {
        int row0 = m0 + wr*32 + i*16 + (lane >> 2);
#pragma unroll
        for (int j = 0; j < 12; j++) {
            int colg = wc*96 + j*8 + (lane & 3)*2;
            __half* dst; const float* bias; int cc; float sc;
            if (colg < 64)       { dst = g_qh; bias = bq; cc = colg;       sc = scale; }
            else if (colg < 128) { dst = g_kh; bias = bk; cc = colg - 64;  sc = 1.f;   }
            else                 { dst = g_vh; bias = bv; cc = colg - 128; sc = 1.f;   }
            float b0 = bias[cc], b1 = bias[cc + 1];
            const float* cp = c + (i*12 + j)*4;
            __half2 v0 = __floats2half2_rn((cp[0] + b0) * sc, (cp[1] + b1) * sc);
            __half2 v1 = __floats2half2_rn((cp[2] + b0) * sc, (cp[3] + b1) * sc);
            *(__half2*)(dst + (size_t)row0 * Hz + cc)       = v0;
            *(__half2*)(dst + (size_t)(row0 + 8) * Hz + cc) = v1;
        }
    }
}

// ---------------------------------------------------------------------------
// attn_hmma: flash-style causal attention, cp.async double-buffered K/V,
// V fragments via ldmatrix.trans (no manual transpose).
// Grid (2 q-blocks of 128, 512 batches), 256 threads = 8 warps, 2 CTAs/SM.
// ---------------------------------------------------------------------------
#define AT_K(buf) (9216 + (buf)*9216)
#define AT_V(buf) (13824 + (buf)*9216)
#define ATT_SMEM (27648*2)   // Q 18KB + 2 x (K 9KB + V 9KB)

#define ATT_PF(kb, buf) { \
    const __half* ks_ = kg + (size_t)(kb) * 64 * Hz; \
    const __half* vs_ = vg + (size_t)(kb) * 64 * Hz; \
    uint32_t kd_ = smb + (uint32_t)AT_K(buf) * 2u; \
    uint32_t vd_ = smb + (uint32_t)AT_V(buf) * 2u; \
    _Pragma("unroll") \
    for (int it = 0; it < 2; it++) { \
        int i = it * 256 + tid; \
        int row = i >> 3, c8 = (i & 7) * 8; \
        cp16(kd_ + (uint32_t)(row * 72 + c8) * 2u, ks_ + row * Hz + c8); \
        cp16(vd_ + (uint32_t)(row * 72 + c8) * 2u, vs_ + row * Hz + c8); \
    } \
    asm volatile("cp.async.commit_group;" ::: "memory"); }

__global__ __launch_bounds__(256, 2) void attn_hmma(float* __restrict__ out)
{
    extern __shared__ __half smh[];
    const uint32_t smb = smem_u32(smh);
    __half* Qs = smh;                 // [128][72]

    const int tid  = threadIdx.x;
    const int w    = tid >> 5;
    const int lane = tid & 31;
    const int batch = blockIdx.y;
    const int qb    = blockIdx.x;
    const int q0    = qb * 128;

    const __half* qg = g_qh + ((size_t)batch * Tz + q0) * Hz;
    const __half* kg = g_kh + (size_t)batch * Tz * Hz;
    const __half* vg = g_vh + (size_t)batch * Tz * Hz;
    const int kbmax = 2 * (qb + 1);

    // prefetch first K/V tile, then stage Q
    ATT_PF(0, 0);
#pragma unroll
    for (int it = 0; it < 4; it++) {
        int i = it * 256 + tid;
        int row = i >> 3, c8 = (i & 7) * 8;
        *(uint4*)&Qs[row * 72 + c8] = *(const uint4*)(qg + row * Hz + c8);
    }
    __syncthreads();

    const int a_row = (lane & 7) + ((lane >> 3) & 1) * 8;
    const int a_k   = (lane >> 4) * 8;
    const int b_n   = (lane & 7) + (lane >> 4) * 8;
    const int b_k   = ((lane >> 3) & 1) * 8;

    uint32_t qf[4][4];
#pragma unroll
    for (int j = 0; j < 4; j++)
        ldsm4(qf[j], smem_u32(&Qs[(w*16 + a_row) * 72 + j*16 + a_k]));

    float o[8][4];
#pragma unroll
    for (int t = 0; t < 8; t++)
#pragma unroll
        for (int p = 0; p < 4; p++) o[t][p] = 0.f;
    float m0 = -1e30f, m1 = -1e30f, l0 = 0.f, l1 = 0.f;

    const int r     = lane >> 2;
    const int cpair = (lane & 3) * 2;
    const int rowg0 = q0 + w*16 + r;

    for (int kb = 0; kb < kbmax; kb++) {
        if (kb + 1 < kbmax) {
            ATT_PF(kb + 1, (kb + 1) & 1);
            asm volatile("cp.async.wait_group 1;" ::: "memory");
        } else {
            asm volatile("cp.async.wait_group 0;" ::: "memory");
        }
        __syncthreads();

        const __half* Ksm = smh + AT_K(kb & 1);
        const __half* Vsm = smh + AT_V(kb & 1);

        if (kb*64 <= q0 + w*16 + 15) {
            // ---- S = Q K^T
            float s[8][4];
#pragma unroll
            for (int t = 0; t < 8; t++)
#pragma unroll
                for (int p = 0; p < 4; p++) s[t][p] = 0.f;
#pragma unroll
            for (int j = 0; j < 4; j++) {
                uint32_t bk4[4][4];
#pragma unroll
                for (int n = 0; n < 4; n++)
                    ldsm4(bk4[n], smem_u32(&Ksm[(n*16 + b_n) * 72 + j*16 + b_k]));
#pragma unroll
                for (int t = 0; t < 8; t++)
                    mma_f16(s[t], qf[j], &bk4[t >> 1][(t & 1) * 2]);
            }
            // ---- causal mask
            if (kb*64 + 63 > q0 + w*16) {
#pragma unroll
                for (int t = 0; t < 8; t++) {
                    int col = kb*64 + t*8 + cpair;
                    if (col     > rowg0)     s[t][0] = -1e30f;
                    if (col + 1 > rowg0)     s[t][1] = -1e30f;
                    if (col     > rowg0 + 8) s[t][2] = -1e30f;
                    if (col + 1 > rowg0 + 8) s[t][3] = -1e30f;
                }
            }
            // ---- online softmax
            float a0 = -1e30f, a1 = -1e30f;
#pragma unroll
            for (int t = 0; t < 8; t++) {
                a0 = fmaxf(a0, fmaxf(s[t][0], s[t][1]));
                a1 = fmaxf(a1, fmaxf(s[t][2], s[t][3]));
            }
            a0 = fmaxf(a0, __shfl_xor_sync(0xffffffffu, a0, 1));
            a0 = fmaxf(a0, __shfl_xor_sync(0xffffffffu, a0, 2));
            a1 = fmaxf(a1, __shfl_xor_sync(0xffffffffu, a1, 1));
            a1 = fmaxf(a1, __shfl_xor_sync(0xffffffffu, a1, 2));
            float mn0 = fmaxf(m0, a0), mn1 = fmaxf(m1, a1);
            float al0 = __expf(m0 - mn0), al1 = __expf(m1 - mn1);
            m0 = mn0; m1 = mn1;
            float rs0 = 0.f, rs1 = 0.f;
#pragma unroll
            for (int t = 0; t < 8; t++) {
                s[t][0] = __expf(s[t][0] - m0);
                s[t][1] = __expf(s[t][1] - m0);
                s[t][2] = __expf(s[t][2] - m1);
                s[t][3] = __expf(s[t][3] - m1);
                rs0 += s[t][0] + s[t][1];
                rs1 += s[t][2] + s[t][3];
            }
            rs0 += __shfl_xor_sync(0xffffffffu, rs0, 1);
            rs0 += __shfl_xor_sync(0xffffffffu, rs0, 2);
            rs1 += __shfl_xor_sync(0xffffffffu, rs1, 1);
            rs1 += __shfl_xor_sync(0xffffffffu, rs1, 2);
            l0 = l0 * al0 + rs0;
            l1 = l1 * al1 + rs1;
#pragma unroll
            for (int t = 0; t < 8; t++) {
                o[t][0] *= al0; o[t][1] *= al0;
                o[t][2] *= al1; o[t][3] *= al1;
            }
            // ---- P C-frags -> fp16 A-frags
            uint32_t pfr[4][4];
#pragma unroll
            for (int j = 0; j < 4; j++) {
                pfr[j][0] = h2pack(s[2*j][0],   s[2*j][1]);
                pfr[j][1] = h2pack(s[2*j][2],   s[2*j][3]);
                pfr[j][2] = h2pack(s[2*j+1][0], s[2*j+1][1]);
                pfr[j][3] = h2pack(s[2*j+1][2], s[2*j+1][3]);
            }
            // ---- O += P V  (V frags via ldmatrix.trans on row-major V)
#pragma unroll
            for (int j = 0; j < 4; j++) {
                uint32_t bv[4][4];
#pragma unroll
                for (int dt = 0; dt < 4; dt++)
                    ldsm4t(bv[dt], smem_u32(&Vsm[(j*16 + a_row) * 72 + dt*16 + a_k]));
#pragma unroll
                for (int t = 0; t < 8; t++)
                    mma_f16(o[t], pfr[j], &bv[t >> 1][(t & 1) * 2]);
            }
        }
        __syncthreads();
    }

    float inv0 = 1.f / l0, inv1 = 1.f / l1;
    float* og0 = out + ((size_t)batch * Tz + rowg0) * Hz;
    float* og1 = og0 + 8 * Hz;
#pragma unroll
    for (int t = 0; t < 8; t++) {
        *(float2*)(og0 + t*8 + cpair) = make_float2(o[t][0] * inv0, o[t][1] * inv0);
        *(float2*)(og1 + t*8 + cpair) = make_float2(o[t][2] * inv1, o[t][3] * inv1);
    }
}

extern "C" void kernel_launch(void* const* d_in, const int* in_sizes, int n_in,
                              void* d_out, int out_size) {
    const float* x  = (const float*)d_in[0];
    const float* Wq = (const float*)d_in[1];
    const float* bq = (const float*)d_in[2];
    const float* Wk = (const float*)d_in[3];
    const float* bk = (const float*)d_in[4];
    const float* Wv = (const float*)d_in[5];
    const float* bv = (const float*)d_in[6];
    float* out = (float*)d_out;

    cudaFuncSetAttribute(qkv_tc,
                         cudaFuncAttributeMaxDynamicSharedMemorySize, QKV_SMEM);
    cudaFuncSetAttribute(attn_hmma,
                         cudaFuncAttributeMaxDynamicSharedMemorySize, ATT_SMEM);

    prep_w<<<(Cz * Nn + 255) / 256, 256>>>(Wq, Wk, Wv);
    qkv_tc<<<BT / 128, 256, QKV_SMEM>>>(x, bq, bk, bv);
    attn_hmma<<<dim3(2, Bz), 256, ATT_SMEM>>>(out);
}